// round 3
// baseline (speedup 1.0000x reference)
#include <cuda_runtime.h>
#include <math.h>

#define N_NODES 6144
#define N_EDGES 196608
#define IN_F    256
#define OUT_F   128
#define EDGE_D  16
#define ALPHA   0.2f
#define MAXD    512

// ---------------- scratch (static device globals; no allocation allowed) ----
__device__ float g_h[N_NODES * OUT_F];     // transformed features
__device__ float g_s1[N_NODES];
__device__ float g_s2[N_NODES];
__device__ float g_es[N_EDGES];
__device__ float g_meanh[OUT_F];
__device__ int   g_count[N_NODES];
__device__ int   g_off[N_NODES];
__device__ int   g_rowptr[N_NODES + 1];
__device__ int   g_col[N_EDGES];
__device__ int   g_eid[N_EDGES];
__device__ int   g_is64;                   // 1 if edge_index is int64, 0 if int32

// ---------------- zero counters + assume-int64 flag -------------------------
__global__ void zero_kernel() {
    int i = blockIdx.x * blockDim.x + threadIdx.x;
    if (i < N_NODES) { g_count[i] = 0; g_off[i] = 0; }
    if (i == 0) g_is64 = 1;
}

// ---------------- dtype probe: are all int64-reads valid node ids? ----------
__global__ void detect_kernel(const void* __restrict__ ei_raw) {
    int e = blockIdx.x * blockDim.x + threadIdx.x;
    if (e >= N_EDGES) return;
    long long v = ((const long long*)ei_raw)[e];
    if (v < 0 || v >= N_NODES) g_is64 = 0;   // benign race: only writes 0
}

__device__ __forceinline__ int load_idx(const void* ei_raw, int row, int e, int is64) {
    int v;
    if (is64) v = (int)((const long long*)ei_raw)[(long long)row * N_EDGES + e];
    else      v = ((const int*)ei_raw)[row * N_EDGES + e];
    // defensive clamp: never form a wild address even if interpretation is wrong
    v = v < 0 ? 0 : (v >= N_NODES ? N_NODES - 1 : v);
    return v;
}

// ---------------- SGEMM: g_h = input_h (6144x256) @ W (256x128) -------------
// BM=32, BN=128, BK=32, 256 threads, each thread computes 4x4.
__global__ __launch_bounds__(256) void gemm_kernel(const float* __restrict__ A,
                                                   const float* __restrict__ B) {
    __shared__ float  As[32][33];     // [k][m], padded
    __shared__ float4 Bs[32][32];     // [k][col4]

    int tid = threadIdx.x;
    int ty  = tid >> 5;               // 0..7  -> rows ty*4 .. ty*4+3
    int tx  = tid & 31;               // 0..31 -> cols tx*4 .. tx*4+3
    int blockRow = blockIdx.x * 32;

    int arow = tid >> 3;              // 0..31
    int ak4  = (tid & 7) * 4;         // 0,4,...,28

    float acc[4][4] = {};

    for (int k0 = 0; k0 < IN_F; k0 += 32) {
        float4 av = *(const float4*)&A[(blockRow + arow) * IN_F + k0 + ak4];
        As[ak4 + 0][arow] = av.x;
        As[ak4 + 1][arow] = av.y;
        As[ak4 + 2][arow] = av.z;
        As[ak4 + 3][arow] = av.w;
#pragma unroll
        for (int r = 0; r < 4; r++) {
            int idx = tid + r * 256;          // 0..1023
            int kb  = idx >> 5;               // 0..31
            int cb  = idx & 31;               // 0..31
            Bs[kb][cb] = *(const float4*)&B[(k0 + kb) * OUT_F + cb * 4];
        }
        __syncthreads();
#pragma unroll
        for (int k = 0; k < 32; k++) {
            float a0 = As[k][ty * 4 + 0];
            float a1 = As[k][ty * 4 + 1];
            float a2 = As[k][ty * 4 + 2];
            float a3 = As[k][ty * 4 + 3];
            float4 bv = Bs[k][tx];
            acc[0][0] += a0 * bv.x; acc[0][1] += a0 * bv.y; acc[0][2] += a0 * bv.z; acc[0][3] += a0 * bv.w;
            acc[1][0] += a1 * bv.x; acc[1][1] += a1 * bv.y; acc[1][2] += a1 * bv.z; acc[1][3] += a1 * bv.w;
            acc[2][0] += a2 * bv.x; acc[2][1] += a2 * bv.y; acc[2][2] += a2 * bv.z; acc[2][3] += a2 * bv.w;
            acc[3][0] += a3 * bv.x; acc[3][1] += a3 * bv.y; acc[3][2] += a3 * bv.z; acc[3][3] += a3 * bv.w;
        }
        __syncthreads();
    }
#pragma unroll
    for (int r = 0; r < 4; r++) {
        float4 v = make_float4(acc[r][0], acc[r][1], acc[r][2], acc[r][3]);
        *(float4*)&g_h[(blockRow + ty * 4 + r) * OUT_F + tx * 4] = v;
    }
}

// ---------------- s1[i] = h_i . a1 ; s2[i] = h_i . a2 (1 warp per node) -----
__global__ void s12_kernel(const float* __restrict__ a) {
    int gt   = blockIdx.x * blockDim.x + threadIdx.x;
    int node = gt >> 5;
    int lane = gt & 31;
    if (node >= N_NODES) return;
    float4 hv = *(const float4*)&g_h[node * OUT_F + lane * 4];
    float4 v1 = *(const float4*)&a[lane * 4];
    float4 v2 = *(const float4*)&a[OUT_F + lane * 4];
    float d1 = hv.x * v1.x + hv.y * v1.y + hv.z * v1.z + hv.w * v1.w;
    float d2 = hv.x * v2.x + hv.y * v2.y + hv.z * v2.z + hv.w * v2.w;
#pragma unroll
    for (int o = 16; o > 0; o >>= 1) {
        d1 += __shfl_xor_sync(0xffffffffu, d1, o);
        d2 += __shfl_xor_sync(0xffffffffu, d2, o);
    }
    if (lane == 0) { g_s1[node] = d1; g_s2[node] = d2; }
}

// ---------------- per-edge score: es[e] = edge_features[e] . a3 -------------
__global__ void es_kernel(const float* __restrict__ ef, const float* __restrict__ a) {
    int e = blockIdx.x * blockDim.x + threadIdx.x;
    if (e >= N_EDGES) return;
    const float* a3 = a + 2 * OUT_F;
    float s = 0.f;
#pragma unroll
    for (int q = 0; q < 4; q++) {
        float4 fv = *(const float4*)&ef[e * EDGE_D + q * 4];
        float4 av = *(const float4*)&a3[q * 4];
        s += fv.x * av.x + fv.y * av.y + fv.z * av.z + fv.w * av.w;
    }
    g_es[e] = s;
}

// ---------------- CSR build: histogram / scan / scatter ---------------------
__global__ void hist_kernel(const void* __restrict__ ei) {
    int e = blockIdx.x * blockDim.x + threadIdx.x;
    if (e >= N_EDGES) return;
    int is64 = g_is64;
    atomicAdd(&g_count[load_idx(ei, 0, e, is64)], 1);
}

__global__ __launch_bounds__(1024) void scan_kernel() {
    __shared__ int sp[1024];
    int t = threadIdx.x;
    int base = t * 6;                 // 1024 * 6 = 6144
    int loc[6];
    int s = 0;
#pragma unroll
    for (int k = 0; k < 6; k++) { loc[k] = s; s += g_count[base + k]; }
    sp[t] = s;
    __syncthreads();
    for (int o = 1; o < 1024; o <<= 1) {
        int v = (t >= o) ? sp[t - o] : 0;
        __syncthreads();
        sp[t] += v;
        __syncthreads();
    }
    int off = (t > 0) ? sp[t - 1] : 0;
#pragma unroll
    for (int k = 0; k < 6; k++) g_rowptr[base + k] = off + loc[k];
    if (t == 1023) g_rowptr[N_NODES] = off + s;
}

__global__ void scatter_kernel(const void* __restrict__ ei) {
    int e = blockIdx.x * blockDim.x + threadIdx.x;
    if (e >= N_EDGES) return;
    int is64 = g_is64;
    int src = load_idx(ei, 0, e, is64);
    int dst = load_idx(ei, 1, e, is64);
    int pos = g_rowptr[src] + atomicAdd(&g_off[src], 1);
    g_col[pos] = dst;
    g_eid[pos] = e;
}

// ---------------- column mean of h (for degree-0 rows) ----------------------
__global__ void meanh_kernel() {
    int f = blockIdx.x;               // 128 blocks
    float s = 0.f;
    for (int i = threadIdx.x; i < N_NODES; i += blockDim.x) s += g_h[i * OUT_F + f];
    __shared__ float red[256];
    red[threadIdx.x] = s;
    __syncthreads();
    for (int o = 128; o > 0; o >>= 1) {
        if (threadIdx.x < o) red[threadIdx.x] += red[threadIdx.x + o];
        __syncthreads();
    }
    if (threadIdx.x == 0) g_meanh[f] = red[0] / (float)N_NODES;
}

// ---------------- main attention kernel: one block (128 thr) per src row ----
__global__ __launch_bounds__(128) void attn_kernel(float* __restrict__ out) {
    __shared__ int   sdst[MAXD];
    __shared__ int   seid[MAXD];
    __shared__ float sw[MAXD];
    __shared__ float red[128];

    int i = blockIdx.x;
    int t = threadIdx.x;
    int start = g_rowptr[i];
    int d = g_rowptr[i + 1] - start;

    if (d == 0) {                     // all-masked row -> uniform softmax
        out[i * OUT_F + t] = g_meanh[t];
        return;
    }
    if (d > MAXD) d = MAXD;           // statistically impossible; safety clamp

    for (int k = t; k < d; k += 128) {
        sdst[k] = g_col[start + k];
        seid[k] = g_eid[start + k];
    }
    __syncthreads();

    float s1i = g_s1[i];
    for (int k = t; k < d; k += 128) {
        int dst = sdst[k];
        int eid = seid[k];
        // dedup duplicate (src,dst): dense scatter counts each pair once;
        // CPU-XLA scatter applies updates in order, so last (max eid) wins.
        bool win = true;
        for (int l = 0; l < d; l++)
            if (sdst[l] == dst && seid[l] > eid) win = false;
        float e;
        if (win) {
            e = s1i + g_s2[dst] + g_es[eid];
            e = (e > 0.f) ? e : ALPHA * e;
        } else {
            e = -1e30f;               // exp underflows to exactly 0
        }
        sw[k] = e;
    }
    __syncthreads();

    // row max
    float m = -1e30f;
    for (int k = t; k < d; k += 128) m = fmaxf(m, sw[k]);
    red[t] = m;
    __syncthreads();
    for (int o = 64; o > 0; o >>= 1) {
        if (t < o) red[t] = fmaxf(red[t], red[t + o]);
        __syncthreads();
    }
    m = red[0];
    __syncthreads();

    // exp + sum
    float z = 0.f;
    for (int k = t; k < d; k += 128) {
        float w = __expf(sw[k] - m);
        sw[k] = w;
        z += w;
    }
    red[t] = z;
    __syncthreads();
    for (int o = 64; o > 0; o >>= 1) {
        if (t < o) red[t] += red[t + o];
        __syncthreads();
    }
    float invz = 1.f / red[0];
    __syncthreads();

    // weighted gather-accumulate: thread t owns output feature t
    float acc = 0.f;
    for (int k = 0; k < d; k++)
        acc += sw[k] * g_h[sdst[k] * OUT_F + t];
    out[i * OUT_F + t] = acc * invz;
}

// ---------------- launch ----------------------------------------------------
extern "C" void kernel_launch(void* const* d_in, const int* in_sizes, int n_in,
                              void* d_out, int out_size) {
    const float* input_h       = (const float*)d_in[0];
    const void*  edge_index    = (const void*)d_in[1];
    const float* edge_features = (const float*)d_in[2];
    const float* W             = (const float*)d_in[3];
    const float* a             = (const float*)d_in[4];
    float* out = (float*)d_out;

    zero_kernel<<<(N_NODES + 1023) / 1024, 1024>>>();
    detect_kernel<<<(N_EDGES + 255) / 256, 256>>>(edge_index);
    gemm_kernel<<<N_NODES / 32, 256>>>(input_h, W);
    s12_kernel<<<(N_NODES * 32) / 256, 256>>>(a);
    es_kernel<<<(N_EDGES + 255) / 256, 256>>>(edge_features, a);
    hist_kernel<<<(N_EDGES + 255) / 256, 256>>>(edge_index);
    scan_kernel<<<1, 1024>>>();
    scatter_kernel<<<(N_EDGES + 255) / 256, 256>>>(edge_index);
    meanh_kernel<<<OUT_F, 256>>>();
    attn_kernel<<<N_NODES, 128>>>(out);
}

// round 4
// speedup vs baseline: 1.1538x; 1.1538x over previous
#include <cuda_runtime.h>
#include <math.h>

#define N_NODES 6144
#define N_EDGES 196608
#define IN_F    256
#define OUT_F   128
#define EDGE_D  16
#define ALPHA   0.2f
#define MAXD    512

// ---------------- scratch (static device globals; no allocation allowed) ----
__device__ float g_h[N_NODES * OUT_F];     // transformed features
__device__ float g_s1[N_NODES];
__device__ float g_s2[N_NODES];
__device__ float g_es[N_EDGES];
__device__ int   g_count[N_NODES];
__device__ int   g_off[N_NODES];
__device__ int   g_rowptr[N_NODES + 1];
__device__ int   g_col[N_EDGES];
__device__ int   g_eid[N_EDGES];
__device__ int   g_is64;                   // 1 if edge_index is int64, 0 if int32

// ---------------- zero counters + assume-int64 flag -------------------------
__global__ void zero_kernel() {
    int i = blockIdx.x * blockDim.x + threadIdx.x;
    if (i < N_NODES) { g_count[i] = 0; g_off[i] = 0; }
    if (i == 0) g_is64 = 1;
}

// ---------------- dtype probe on a prefix (8192 slots is conclusive) --------
__global__ void detect_kernel(const void* __restrict__ ei_raw) {
    int e = blockIdx.x * blockDim.x + threadIdx.x;   // 8192 threads
    long long v = ((const long long*)ei_raw)[e];
    if (v < 0 || v >= N_NODES) g_is64 = 0;           // benign race: only writes 0
}

__device__ __forceinline__ int load_idx(const void* ei_raw, int row, int e, int is64) {
    int v;
    if (is64) v = (int)((const long long*)ei_raw)[(long long)row * N_EDGES + e];
    else      v = ((const int*)ei_raw)[row * N_EDGES + e];
    v = v < 0 ? 0 : (v >= N_NODES ? N_NODES - 1 : v);   // never form a wild address
    return v;
}

// ---------------- SGEMM + fused s1/s2 epilogue ------------------------------
// g_h = input_h (6144x256) @ W (256x128); s1 = h@a1, s2 = h@a2.
// BM=32, BN=128, BK=32, 256 threads, each thread computes 4x4.
// Warp `ty` owns rows ty*4..ty*4+3 across all 128 cols (lanes = tx) -> the
// a1/a2 dot products are two warp reductions over the accumulators.
__global__ __launch_bounds__(256) void gemm_kernel(const float* __restrict__ A,
                                                   const float* __restrict__ B,
                                                   const float* __restrict__ a) {
    __shared__ float  As[32][33];     // [k][m], padded
    __shared__ float4 Bs[32][32];     // [k][col4]

    int tid = threadIdx.x;
    int ty  = tid >> 5;               // 0..7  -> rows ty*4 .. ty*4+3
    int tx  = tid & 31;               // 0..31 -> cols tx*4 .. tx*4+3
    int blockRow = blockIdx.x * 32;

    int arow = tid >> 3;              // 0..31
    int ak4  = (tid & 7) * 4;         // 0,4,...,28

    float acc[4][4] = {};

    for (int k0 = 0; k0 < IN_F; k0 += 32) {
        float4 av = *(const float4*)&A[(blockRow + arow) * IN_F + k0 + ak4];
        As[ak4 + 0][arow] = av.x;
        As[ak4 + 1][arow] = av.y;
        As[ak4 + 2][arow] = av.z;
        As[ak4 + 3][arow] = av.w;
#pragma unroll
        for (int r = 0; r < 4; r++) {
            int idx = tid + r * 256;          // 0..1023
            int kb  = idx >> 5;               // 0..31
            int cb  = idx & 31;               // 0..31
            Bs[kb][cb] = *(const float4*)&B[(k0 + kb) * OUT_F + cb * 4];
        }
        __syncthreads();
#pragma unroll
        for (int k = 0; k < 32; k++) {
            float a0 = As[k][ty * 4 + 0];
            float a1 = As[k][ty * 4 + 1];
            float a2 = As[k][ty * 4 + 2];
            float a3 = As[k][ty * 4 + 3];
            float4 bv = Bs[k][tx];
            acc[0][0] += a0 * bv.x; acc[0][1] += a0 * bv.y; acc[0][2] += a0 * bv.z; acc[0][3] += a0 * bv.w;
            acc[1][0] += a1 * bv.x; acc[1][1] += a1 * bv.y; acc[1][2] += a1 * bv.z; acc[1][3] += a1 * bv.w;
            acc[2][0] += a2 * bv.x; acc[2][1] += a2 * bv.y; acc[2][2] += a2 * bv.z; acc[2][3] += a2 * bv.w;
            acc[3][0] += a3 * bv.x; acc[3][1] += a3 * bv.y; acc[3][2] += a3 * bv.z; acc[3][3] += a3 * bv.w;
        }
        __syncthreads();
    }

    // store h tile
#pragma unroll
    for (int r = 0; r < 4; r++) {
        float4 v = make_float4(acc[r][0], acc[r][1], acc[r][2], acc[r][3]);
        *(float4*)&g_h[(blockRow + ty * 4 + r) * OUT_F + tx * 4] = v;
    }

    // fused s1/s2: per-row dot with a1/a2, reduced across the warp
    float4 a1v = *(const float4*)&a[tx * 4];
    float4 a2v = *(const float4*)&a[OUT_F + tx * 4];
#pragma unroll
    for (int r = 0; r < 4; r++) {
        float p1 = acc[r][0] * a1v.x + acc[r][1] * a1v.y + acc[r][2] * a1v.z + acc[r][3] * a1v.w;
        float p2 = acc[r][0] * a2v.x + acc[r][1] * a2v.y + acc[r][2] * a2v.z + acc[r][3] * a2v.w;
#pragma unroll
        for (int o = 16; o > 0; o >>= 1) {
            p1 += __shfl_xor_sync(0xffffffffu, p1, o);
            p2 += __shfl_xor_sync(0xffffffffu, p2, o);
        }
        if (tx == 0) {
            int row = blockRow + ty * 4 + r;
            g_s1[row] = p1;
            g_s2[row] = p2;
        }
    }
}

// ---------------- fused per-edge: es[e] = ef[e].a3 ; histogram src ----------
__global__ void edge_kernel(const float* __restrict__ ef, const float* __restrict__ a,
                            const void* __restrict__ ei) {
    int e = blockIdx.x * blockDim.x + threadIdx.x;
    if (e >= N_EDGES) return;
    const float* a3 = a + 2 * OUT_F;
    float s = 0.f;
#pragma unroll
    for (int q = 0; q < 4; q++) {
        float4 fv = *(const float4*)&ef[e * EDGE_D + q * 4];
        float4 av = *(const float4*)&a3[q * 4];
        s += fv.x * av.x + fv.y * av.y + fv.z * av.z + fv.w * av.w;
    }
    g_es[e] = s;
    int is64 = g_is64;
    atomicAdd(&g_count[load_idx(ei, 0, e, is64)], 1);
}

// ---------------- scan: 1024 threads, shfl hierarchy, 2 barriers ------------
__global__ __launch_bounds__(1024) void scan_kernel() {
    __shared__ int wsum[32];
    int t    = threadIdx.x;
    int lane = t & 31;
    int wid  = t >> 5;
    int base = t * 6;                 // 1024 * 6 = 6144
    int loc[6];
    int s = 0;
#pragma unroll
    for (int k = 0; k < 6; k++) { loc[k] = s; s += g_count[base + k]; }

    // warp-inclusive scan of s
    int inc = s;
#pragma unroll
    for (int o = 1; o < 32; o <<= 1) {
        int v = __shfl_up_sync(0xffffffffu, inc, o);
        if (lane >= o) inc += v;
    }
    if (lane == 31) wsum[wid] = inc;
    __syncthreads();

    if (wid == 0) {
        int w = wsum[lane];
        int wi = w;
#pragma unroll
        for (int o = 1; o < 32; o <<= 1) {
            int v = __shfl_up_sync(0xffffffffu, wi, o);
            if (lane >= o) wi += v;
        }
        wsum[lane] = wi;
    }
    __syncthreads();

    int off = (wid > 0 ? wsum[wid - 1] : 0) + (inc - s);   // exclusive prefix
#pragma unroll
    for (int k = 0; k < 6; k++) g_rowptr[base + k] = off + loc[k];
    if (t == 1023) g_rowptr[N_NODES] = off + s;
}

__global__ void scatter_kernel(const void* __restrict__ ei) {
    int e = blockIdx.x * blockDim.x + threadIdx.x;
    if (e >= N_EDGES) return;
    int is64 = g_is64;
    int src = load_idx(ei, 0, e, is64);
    int dst = load_idx(ei, 1, e, is64);
    int pos = g_rowptr[src] + atomicAdd(&g_off[src], 1);
    g_col[pos] = dst;
    g_eid[pos] = e;
}

// ---------------- main attention kernel: one block (128 thr) per src row ----
__global__ __launch_bounds__(128) void attn_kernel(float* __restrict__ out) {
    __shared__ int   sdst[MAXD];
    __shared__ int   seid[MAXD];
    __shared__ float sw[MAXD];
    __shared__ float red[128];

    int i = blockIdx.x;
    int t = threadIdx.x;
    int start = g_rowptr[i];
    int d = g_rowptr[i + 1] - start;

    if (d == 0) {                     // all-masked row -> uniform softmax = column mean
        float s = 0.f;
        for (int n = 0; n < N_NODES; n++) s += g_h[n * OUT_F + t];
        out[i * OUT_F + t] = s / (float)N_NODES;
        return;
    }
    if (d > MAXD) d = MAXD;           // statistically impossible; safety clamp

    for (int k = t; k < d; k += 128) {
        sdst[k] = g_col[start + k];
        seid[k] = g_eid[start + k];
    }
    __syncthreads();

    float s1i = g_s1[i];
    for (int k = t; k < d; k += 128) {
        int dst = sdst[k];
        int eid = seid[k];
        // dedup duplicate (src,dst): dense scatter counts each pair once;
        // updates apply in order, so last (max eid) wins.
        bool win = true;
        for (int l = 0; l < d; l++)
            if (sdst[l] == dst && seid[l] > eid) win = false;
        float e;
        if (win) {
            e = s1i + g_s2[dst] + g_es[eid];
            e = (e > 0.f) ? e : ALPHA * e;
        } else {
            e = -1e30f;               // exp underflows to exactly 0
        }
        sw[k] = e;
    }
    __syncthreads();

    // row max
    float m = -1e30f;
    for (int k = t; k < d; k += 128) m = fmaxf(m, sw[k]);
    red[t] = m;
    __syncthreads();
    for (int o = 64; o > 0; o >>= 1) {
        if (t < o) red[t] = fmaxf(red[t], red[t + o]);
        __syncthreads();
    }
    m = red[0];
    __syncthreads();

    // exp + sum
    float z = 0.f;
    for (int k = t; k < d; k += 128) {
        float w = __expf(sw[k] - m);
        sw[k] = w;
        z += w;
    }
    red[t] = z;
    __syncthreads();
    for (int o = 64; o > 0; o >>= 1) {
        if (t < o) red[t] += red[t + o];
        __syncthreads();
    }
    float invz = 1.f / red[0];
    __syncthreads();

    // weighted gather-accumulate: thread t owns output feature t
    float acc = 0.f;
    for (int k = 0; k < d; k++)
        acc += sw[k] * g_h[sdst[k] * OUT_F + t];
    out[i * OUT_F + t] = acc * invz;
}

// ---------------- launch ----------------------------------------------------
extern "C" void kernel_launch(void* const* d_in, const int* in_sizes, int n_in,
                              void* d_out, int out_size) {
    const float* input_h       = (const float*)d_in[0];
    const void*  edge_index    = (const void*)d_in[1];
    const float* edge_features = (const float*)d_in[2];
    const float* W             = (const float*)d_in[3];
    const float* a             = (const float*)d_in[4];
    float* out = (float*)d_out;

    zero_kernel<<<(N_NODES + 1023) / 1024, 1024>>>();
    detect_kernel<<<8, 1024>>>(edge_index);
    gemm_kernel<<<N_NODES / 32, 256>>>(input_h, W, a);
    edge_kernel<<<(N_EDGES + 255) / 256, 256>>>(edge_features, a, edge_index);
    scan_kernel<<<1, 1024>>>();
    scatter_kernel<<<(N_EDGES + 255) / 256, 256>>>(edge_index);
    attn_kernel<<<N_NODES, 128>>>(out);
}

// round 6
// speedup vs baseline: 1.3103x; 1.1357x over previous
#include <cuda_runtime.h>
#include <math.h>

#define N_NODES 6144
#define N_EDGES 196608
#define IN_F    256
#define OUT_F   128
#define EDGE_D  16
#define ALPHA   0.2f
#define CAP     128          // per-row bucket capacity (Poisson(32) tail @128 ~ e^-85)

// ---------------- scratch (static device globals; no allocation allowed) ----
__device__ float g_h[N_NODES * OUT_F];       // transformed features
__device__ float g_s1[N_NODES];
__device__ float g_s2[N_NODES];
__device__ int   g_off[N_NODES];             // per-row fill count
__device__ int   g_bdst[N_NODES * CAP];      // bucket: dst node
__device__ int   g_beid[N_NODES * CAP];      // bucket: edge id (dedup tie-break)
__device__ float g_bes [N_NODES * CAP];      // bucket: edge score
__device__ int   g_is64 = 1;                 // dtype flag: only ever cleared

// ---------------- init: zero bucket counts + dtype probe --------------------
// 8192 threads. Probe: an int32 buffer reinterpreted as int64 yields values
// outside [0,N_NODES) with overwhelming probability per slot; 8192 slots is
// conclusive. Flag is static-initialized and only cleared (no race), and the
// input dtype is constant across graph replays, so persistence is safe.
__global__ void init_kernel(const void* __restrict__ ei_raw) {
    int i = blockIdx.x * blockDim.x + threadIdx.x;
    if (i < N_NODES) g_off[i] = 0;
    long long v = ((const long long*)ei_raw)[i];
    if (v < 0 || v >= N_NODES) g_is64 = 0;
}

__device__ __forceinline__ int load_idx(const void* ei_raw, int row, int e, int is64) {
    int v;
    if (is64) v = (int)((const long long*)ei_raw)[(long long)row * N_EDGES + e];
    else      v = ((const int*)ei_raw)[row * N_EDGES + e];
    v = v < 0 ? 0 : (v >= N_NODES ? N_NODES - 1 : v);   // never form a wild address
    return v;
}

// ---------------- SGEMM + fused s1/s2 epilogue ------------------------------
// g_h = input_h (6144x256) @ W (256x128); s1 = h@a1, s2 = h@a2.
// BM=32, BN=128, BK=32, 256 threads, each thread computes 4x4.
__global__ __launch_bounds__(256) void gemm_kernel(const float* __restrict__ A,
                                                   const float* __restrict__ B,
                                                   const float* __restrict__ a) {
    __shared__ float  As[32][33];     // [k][m], padded
    __shared__ float4 Bs[32][32];     // [k][col4]

    int tid = threadIdx.x;
    int ty  = tid >> 5;               // 0..7  -> rows ty*4 .. ty*4+3
    int tx  = tid & 31;               // 0..31 -> cols tx*4 .. tx*4+3
    int blockRow = blockIdx.x * 32;

    int arow = tid >> 3;              // 0..31
    int ak4  = (tid & 7) * 4;         // 0,4,...,28

    float acc[4][4] = {};

    for (int k0 = 0; k0 < IN_F; k0 += 32) {
        float4 av = *(const float4*)&A[(blockRow + arow) * IN_F + k0 + ak4];
        As[ak4 + 0][arow] = av.x;
        As[ak4 + 1][arow] = av.y;
        As[ak4 + 2][arow] = av.z;
        As[ak4 + 3][arow] = av.w;
#pragma unroll
        for (int r = 0; r < 4; r++) {
            int idx = tid + r * 256;          // 0..1023
            int kb  = idx >> 5;               // 0..31
            int cb  = idx & 31;               // 0..31
            Bs[kb][cb] = *(const float4*)&B[(k0 + kb) * OUT_F + cb * 4];
        }
        __syncthreads();
#pragma unroll
        for (int k = 0; k < 32; k++) {
            float a0 = As[k][ty * 4 + 0];
            float a1 = As[k][ty * 4 + 1];
            float a2 = As[k][ty * 4 + 2];
            float a3 = As[k][ty * 4 + 3];
            float4 bv = Bs[k][tx];
            acc[0][0] += a0 * bv.x; acc[0][1] += a0 * bv.y; acc[0][2] += a0 * bv.z; acc[0][3] += a0 * bv.w;
            acc[1][0] += a1 * bv.x; acc[1][1] += a1 * bv.y; acc[1][2] += a1 * bv.z; acc[1][3] += a1 * bv.w;
            acc[2][0] += a2 * bv.x; acc[2][1] += a2 * bv.y; acc[2][2] += a2 * bv.z; acc[2][3] += a2 * bv.w;
            acc[3][0] += a3 * bv.x; acc[3][1] += a3 * bv.y; acc[3][2] += a3 * bv.z; acc[3][3] += a3 * bv.w;
        }
        __syncthreads();
    }

#pragma unroll
    for (int r = 0; r < 4; r++) {
        float4 v = make_float4(acc[r][0], acc[r][1], acc[r][2], acc[r][3]);
        *(float4*)&g_h[(blockRow + ty * 4 + r) * OUT_F + tx * 4] = v;
    }

    // fused s1/s2: per-row dot with a1/a2, reduced across the warp
    float4 a1v = *(const float4*)&a[tx * 4];
    float4 a2v = *(const float4*)&a[OUT_F + tx * 4];
#pragma unroll
    for (int r = 0; r < 4; r++) {
        float p1 = acc[r][0] * a1v.x + acc[r][1] * a1v.y + acc[r][2] * a1v.z + acc[r][3] * a1v.w;
        float p2 = acc[r][0] * a2v.x + acc[r][1] * a2v.y + acc[r][2] * a2v.z + acc[r][3] * a2v.w;
#pragma unroll
        for (int o = 16; o > 0; o >>= 1) {
            p1 += __shfl_xor_sync(0xffffffffu, p1, o);
            p2 += __shfl_xor_sync(0xffffffffu, p2, o);
        }
        if (tx == 0) {
            int row = blockRow + ty * 4 + r;
            g_s1[row] = p1;
            g_s2[row] = p2;
        }
    }
}

// ---------------- fused edge pass: es + direct bucket scatter ---------------
// 4 edges per thread (contiguous 256B of edge_features per thread) for MLP.
#define E_PER 4
__global__ __launch_bounds__(256) void edge_kernel(const float* __restrict__ ef,
                                                   const float* __restrict__ a,
                                                   const void* __restrict__ ei) {
    int t = blockIdx.x * blockDim.x + threadIdx.x;
    int base = t * E_PER;
    if (base >= N_EDGES) return;
    int is64 = g_is64;

    const float* a3 = a + 2 * OUT_F;
    float4 av0 = *(const float4*)&a3[0];
    float4 av1 = *(const float4*)&a3[4];
    float4 av2 = *(const float4*)&a3[8];
    float4 av3 = *(const float4*)&a3[12];

    // load all features first (16 independent float4 loads in flight)
    float4 fv[E_PER][4];
#pragma unroll
    for (int j = 0; j < E_PER; j++) {
#pragma unroll
        for (int q = 0; q < 4; q++)
            fv[j][q] = *(const float4*)&ef[(base + j) * EDGE_D + q * 4];
    }
    int src[E_PER], dst[E_PER];
#pragma unroll
    for (int j = 0; j < E_PER; j++) {
        src[j] = load_idx(ei, 0, base + j, is64);
        dst[j] = load_idx(ei, 1, base + j, is64);
    }
#pragma unroll
    for (int j = 0; j < E_PER; j++) {
        float s = fv[j][0].x * av0.x + fv[j][0].y * av0.y + fv[j][0].z * av0.z + fv[j][0].w * av0.w
                + fv[j][1].x * av1.x + fv[j][1].y * av1.y + fv[j][1].z * av1.z + fv[j][1].w * av1.w
                + fv[j][2].x * av2.x + fv[j][2].y * av2.y + fv[j][2].z * av2.z + fv[j][2].w * av2.w
                + fv[j][3].x * av3.x + fv[j][3].y * av3.y + fv[j][3].z * av3.z + fv[j][3].w * av3.w;
        int pos = atomicAdd(&g_off[src[j]], 1);
        if (pos < CAP) {
            int slot = src[j] * CAP + pos;
            g_bdst[slot] = dst[j];
            g_beid[slot] = base + j;
            g_bes [slot] = s;
        }
    }
}

// ---------------- main attention kernel: one block (128 thr) per src row ----
__global__ __launch_bounds__(128) void attn_kernel(float* __restrict__ out) {
    __shared__ int   sdst[CAP];
    __shared__ int   seid[CAP];
    __shared__ float sw[CAP];
    __shared__ float red[128];

    int i = blockIdx.x;
    int t = threadIdx.x;
    int d = g_off[i];
    if (d > CAP) d = CAP;

    if (d == 0) {                     // all-masked row -> uniform softmax = column mean
        float s = 0.f;
        for (int n = 0; n < N_NODES; n++) s += g_h[n * OUT_F + t];
        out[i * OUT_F + t] = s / (float)N_NODES;
        return;
    }

    float s1i = g_s1[i];
    if (t < d) {
        int slot = i * CAP + t;
        sdst[t] = g_bdst[slot];
        seid[t] = g_beid[slot];
        sw[t]   = g_bes [slot];
    }
    __syncthreads();

    float e = -1e30f;
    if (t < d) {
        int dst = sdst[t];
        int eid = seid[t];
        // dedup duplicate (src,dst): dense scatter counts each pair once;
        // updates apply in order, so last (max eid) wins.
        bool win = true;
        for (int l = 0; l < d; l++)
            if (sdst[l] == dst && seid[l] > eid) win = false;
        if (win) {
            e = s1i + g_s2[dst] + sw[t];
            e = (e > 0.f) ? e : ALPHA * e;
        }
    }
    __syncthreads();
    if (t < d) sw[t] = e;

    // row max
    red[t] = e;
    __syncthreads();
    for (int o = 64; o > 0; o >>= 1) {
        if (t < o) red[t] = fmaxf(red[t], red[t + o]);
        __syncthreads();
    }
    float m = red[0];
    __syncthreads();

    // exp + sum
    float w = (t < d) ? __expf(sw[t] - m) : 0.f;
    if (t < d) sw[t] = w;
    red[t] = w;
    __syncthreads();
    for (int o = 64; o > 0; o >>= 1) {
        if (t < o) red[t] += red[t + o];
        __syncthreads();
    }
    float invz = 1.f / red[0];
    __syncthreads();

    // weighted gather-accumulate: thread t owns output feature t
    float acc = 0.f;
    for (int k = 0; k < d; k++)
        acc += sw[k] * g_h[sdst[k] * OUT_F + t];
    out[i * OUT_F + t] = acc * invz;
}

// ---------------- launch ----------------------------------------------------
extern "C" void kernel_launch(void* const* d_in, const int* in_sizes, int n_in,
                              void* d_out, int out_size) {
    const float* input_h       = (const float*)d_in[0];
    const void*  edge_index    = (const void*)d_in[1];
    const float* edge_features = (const float*)d_in[2];
    const float* W             = (const float*)d_in[3];
    const float* a             = (const float*)d_in[4];
    float* out = (float*)d_out;

    init_kernel<<<8, 1024>>>(edge_index);
    gemm_kernel<<<N_NODES / 32, 256>>>(input_h, W, a);
    edge_kernel<<<N_EDGES / (256 * E_PER), 256>>>(edge_features, a, edge_index);
    attn_kernel<<<N_NODES, 128>>>(out);
}

// round 7
// speedup vs baseline: 1.5072x; 1.1502x over previous
#include <cuda_runtime.h>
#include <math.h>

#define N_NODES 6144
#define N_EDGES 196608
#define IN_F    256
#define OUT_F   128
#define EDGE_D  16
#define ALPHA   0.2f
#define CAP     128          // per-row bucket capacity (Poisson(32) tail @128 ~ e^-85)

// ---------------- scratch (static device globals; no allocation allowed) ----
__device__ float g_h[N_NODES * OUT_F];       // transformed features
__device__ float g_s1[N_NODES];
__device__ float g_s2[N_NODES];
__device__ int   g_off[N_NODES];             // per-row fill count
__device__ int   g_bdst[N_NODES * CAP];      // bucket: dst node
__device__ int   g_beid[N_NODES * CAP];      // bucket: edge id (dedup tie-break)
__device__ float g_bes [N_NODES * CAP];      // bucket: edge score
__device__ int   g_is64 = 1;                 // dtype flag: only ever cleared

// ---------------- init: zero bucket counts + dtype probe --------------------
__global__ void init_kernel(const void* __restrict__ ei_raw) {
    int i = blockIdx.x * blockDim.x + threadIdx.x;
    if (i < N_NODES) g_off[i] = 0;
    long long v = ((const long long*)ei_raw)[i];
    if (v < 0 || v >= N_NODES) g_is64 = 0;   // benign: only ever cleared
}

__device__ __forceinline__ int load_idx(const void* ei_raw, int row, int e, int is64) {
    int v;
    if (is64) v = (int)((const long long*)ei_raw)[(long long)row * N_EDGES + e];
    else      v = ((const int*)ei_raw)[row * N_EDGES + e];
    v = v < 0 ? 0 : (v >= N_NODES ? N_NODES - 1 : v);   // never form a wild address
    return v;
}

// ---------------- SGEMM + fused s1/s2 epilogue ------------------------------
__global__ __launch_bounds__(256) void gemm_kernel(const float* __restrict__ A,
                                                   const float* __restrict__ B,
                                                   const float* __restrict__ a) {
    __shared__ float  As[32][33];     // [k][m], padded
    __shared__ float4 Bs[32][32];     // [k][col4]

    int tid = threadIdx.x;
    int ty  = tid >> 5;               // 0..7  -> rows ty*4 .. ty*4+3
    int tx  = tid & 31;               // 0..31 -> cols tx*4 .. tx*4+3
    int blockRow = blockIdx.x * 32;

    int arow = tid >> 3;              // 0..31
    int ak4  = (tid & 7) * 4;         // 0,4,...,28

    float acc[4][4] = {};

    for (int k0 = 0; k0 < IN_F; k0 += 32) {
        float4 av = *(const float4*)&A[(blockRow + arow) * IN_F + k0 + ak4];
        As[ak4 + 0][arow] = av.x;
        As[ak4 + 1][arow] = av.y;
        As[ak4 + 2][arow] = av.z;
        As[ak4 + 3][arow] = av.w;
#pragma unroll
        for (int r = 0; r < 4; r++) {
            int idx = tid + r * 256;          // 0..1023
            int kb  = idx >> 5;               // 0..31
            int cb  = idx & 31;               // 0..31
            Bs[kb][cb] = *(const float4*)&B[(k0 + kb) * OUT_F + cb * 4];
        }
        __syncthreads();
#pragma unroll
        for (int k = 0; k < 32; k++) {
            float a0 = As[k][ty * 4 + 0];
            float a1 = As[k][ty * 4 + 1];
            float a2 = As[k][ty * 4 + 2];
            float a3 = As[k][ty * 4 + 3];
            float4 bv = Bs[k][tx];
            acc[0][0] += a0 * bv.x; acc[0][1] += a0 * bv.y; acc[0][2] += a0 * bv.z; acc[0][3] += a0 * bv.w;
            acc[1][0] += a1 * bv.x; acc[1][1] += a1 * bv.y; acc[1][2] += a1 * bv.z; acc[1][3] += a1 * bv.w;
            acc[2][0] += a2 * bv.x; acc[2][1] += a2 * bv.y; acc[2][2] += a2 * bv.z; acc[2][3] += a2 * bv.w;
            acc[3][0] += a3 * bv.x; acc[3][1] += a3 * bv.y; acc[3][2] += a3 * bv.z; acc[3][3] += a3 * bv.w;
        }
        __syncthreads();
    }

#pragma unroll
    for (int r = 0; r < 4; r++) {
        float4 v = make_float4(acc[r][0], acc[r][1], acc[r][2], acc[r][3]);
        *(float4*)&g_h[(blockRow + ty * 4 + r) * OUT_F + tx * 4] = v;
    }

    float4 a1v = *(const float4*)&a[tx * 4];
    float4 a2v = *(const float4*)&a[OUT_F + tx * 4];
#pragma unroll
    for (int r = 0; r < 4; r++) {
        float p1 = acc[r][0] * a1v.x + acc[r][1] * a1v.y + acc[r][2] * a1v.z + acc[r][3] * a1v.w;
        float p2 = acc[r][0] * a2v.x + acc[r][1] * a2v.y + acc[r][2] * a2v.z + acc[r][3] * a2v.w;
#pragma unroll
        for (int o = 16; o > 0; o >>= 1) {
            p1 += __shfl_xor_sync(0xffffffffu, p1, o);
            p2 += __shfl_xor_sync(0xffffffffu, p2, o);
        }
        if (tx == 0) {
            int row = blockRow + ty * 4 + r;
            g_s1[row] = p1;
            g_s2[row] = p2;
        }
    }
}

// ---------------- fused edge pass: es + direct bucket scatter ---------------
#define E_PER 4
__global__ __launch_bounds__(256) void edge_kernel(const float* __restrict__ ef,
                                                   const float* __restrict__ a,
                                                   const void* __restrict__ ei) {
    int t = blockIdx.x * blockDim.x + threadIdx.x;
    int base = t * E_PER;
    if (base >= N_EDGES) return;
    int is64 = g_is64;

    const float* a3 = a + 2 * OUT_F;
    float4 av0 = *(const float4*)&a3[0];
    float4 av1 = *(const float4*)&a3[4];
    float4 av2 = *(const float4*)&a3[8];
    float4 av3 = *(const float4*)&a3[12];

    float4 fv[E_PER][4];
#pragma unroll
    for (int j = 0; j < E_PER; j++) {
#pragma unroll
        for (int q = 0; q < 4; q++)
            fv[j][q] = *(const float4*)&ef[(base + j) * EDGE_D + q * 4];
    }
    int src[E_PER], dst[E_PER];
#pragma unroll
    for (int j = 0; j < E_PER; j++) {
        src[j] = load_idx(ei, 0, base + j, is64);
        dst[j] = load_idx(ei, 1, base + j, is64);
    }
#pragma unroll
    for (int j = 0; j < E_PER; j++) {
        float s = fv[j][0].x * av0.x + fv[j][0].y * av0.y + fv[j][0].z * av0.z + fv[j][0].w * av0.w
                + fv[j][1].x * av1.x + fv[j][1].y * av1.y + fv[j][1].z * av1.z + fv[j][1].w * av1.w
                + fv[j][2].x * av2.x + fv[j][2].y * av2.y + fv[j][2].z * av2.z + fv[j][2].w * av2.w
                + fv[j][3].x * av3.x + fv[j][3].y * av3.y + fv[j][3].z * av3.z + fv[j][3].w * av3.w;
        int pos = atomicAdd(&g_off[src[j]], 1);
        if (pos < CAP) {
            int slot = src[j] * CAP + pos;
            g_bdst[slot] = dst[j];
            g_beid[slot] = base + j;
            g_bes [slot] = s;
        }
    }
}

// ---------------- main attention kernel: one block (128 thr) per src row ----
// Softmax by warp 0 (strided LDS + shfl). Gather: 4 warps x 32 lanes, warp g
// takes edges k = g, g+4, ..., lane l owns features 4l..4l+3 (float4 loads).
__global__ __launch_bounds__(128) void attn_kernel(float* __restrict__ out) {
    __shared__ int    sdst[CAP];
    __shared__ int    seid[CAP];
    __shared__ float  sw[CAP];
    __shared__ float  sinvz;
    __shared__ float4 racc[4][32];

    int i = blockIdx.x;
    int t = threadIdx.x;
    int g = t >> 5;                   // warp / edge-group
    int l = t & 31;                   // lane / feature chunk
    int d = g_off[i];
    if (d > CAP) d = CAP;

    if (d == 0) {                     // all-masked row -> uniform softmax = column mean
        float s = 0.f;
        for (int n = 0; n < N_NODES; n++) s += g_h[n * OUT_F + t];
        out[i * OUT_F + t] = s / (float)N_NODES;
        return;
    }

    float s1i = g_s1[i];
    if (t < d) {
        int slot = i * CAP + t;
        sdst[t] = g_bdst[slot];
        seid[t] = g_beid[slot];
        sw[t]   = g_bes [slot];
    }
    __syncthreads();

    if (t < d) {
        int dst = sdst[t];
        int eid = seid[t];
        // dedup duplicate (src,dst): last-written (max eid) edge wins.
        bool win = true;
        for (int k = 0; k < d; k++)
            if (sdst[k] == dst && seid[k] > eid) win = false;
        float e = -1e30f;
        if (win) {
            e = s1i + g_s2[dst] + sw[t];
            e = (e > 0.f) ? e : ALPHA * e;
        }
        sw[t] = e;
    }
    __syncthreads();

    // warp 0: row softmax (max, exp, sum) over d entries
    if (g == 0) {
        float v[4];
        float m = -1e30f;
#pragma unroll
        for (int j = 0; j < 4; j++) {
            int k = l + 32 * j;
            v[j] = (k < d) ? sw[k] : -1e30f;
            m = fmaxf(m, v[j]);
        }
#pragma unroll
        for (int o = 16; o > 0; o >>= 1) m = fmaxf(m, __shfl_xor_sync(0xffffffffu, m, o));
        float z = 0.f;
#pragma unroll
        for (int j = 0; j < 4; j++) {
            int k = l + 32 * j;
            if (k < d) {
                float w = __expf(v[j] - m);
                sw[k] = w;
                z += w;
            }
        }
#pragma unroll
        for (int o = 16; o > 0; o >>= 1) z += __shfl_xor_sync(0xffffffffu, z, o);
        if (l == 0) sinvz = 1.f / z;
    }
    __syncthreads();

    // gather: warp g handles edges g, g+4, ...; float4 per lane
    const float4* h4 = (const float4*)g_h;
    float4 acc = make_float4(0.f, 0.f, 0.f, 0.f);
    for (int k = g; k < d; k += 4) {
        float  wk  = sw[k];
        int    dst = sdst[k];
        float4 hv  = h4[dst * 32 + l];
        acc.x += wk * hv.x; acc.y += wk * hv.y; acc.z += wk * hv.z; acc.w += wk * hv.w;
    }
    racc[g][l] = acc;
    __syncthreads();

    if (g == 0) {
        float4 a0 = racc[0][l], a1 = racc[1][l], a2 = racc[2][l], a3 = racc[3][l];
        float invz = sinvz;
        float4 o;
        o.x = (a0.x + a1.x + a2.x + a3.x) * invz;
        o.y = (a0.y + a1.y + a2.y + a3.y) * invz;
        o.z = (a0.z + a1.z + a2.z + a3.z) * invz;
        o.w = (a0.w + a1.w + a2.w + a3.w) * invz;
        ((float4*)out)[i * 32 + l] = o;
    }
}

// ---------------- launch ----------------------------------------------------
extern "C" void kernel_launch(void* const* d_in, const int* in_sizes, int n_in,
                              void* d_out, int out_size) {
    const float* input_h       = (const float*)d_in[0];
    const void*  edge_index    = (const void*)d_in[1];
    const float* edge_features = (const float*)d_in[2];
    const float* W             = (const float*)d_in[3];
    const float* a             = (const float*)d_in[4];
    float* out = (float*)d_out;

    init_kernel<<<8, 1024>>>(edge_index);
    gemm_kernel<<<N_NODES / 32, 256>>>(input_h, W, a);
    edge_kernel<<<N_EDGES / (256 * E_PER), 256>>>(edge_features, a, edge_index);
    attn_kernel<<<N_NODES, 128>>>(out);
}